// round 5
// baseline (speedup 1.0000x reference)
#include <cuda_runtime.h>
#include <cuda_bf16.h>
#include <cstdint>

#define BB 2048
#define TT 26
#define DD 512
#define HH 512
#define EE 256
#define NC 97
#define SS 32
#define GG 2048   // 4*H
#define KC 1024   // concat K = D + H

// ---------------- scratch (static device memory; no allocations) ----------------
__device__ alignas(256) float g_Hp[(size_t)BB*TT*HH];
__device__ alignas(256) float g_c[(size_t)BB*HH];
__device__ alignas(256) float g_ph[(size_t)BB*HH];
__device__ alignas(256) float g_gates[(size_t)BB*GG];
__device__ alignas(256) float g_bias[GG];
__device__ alignas(256) float g_embproj[(size_t)NC*GG];
// bf16 split-triple operands. A-side sections: [hi | lo | hi]. B-side: [hi | hi | lo].
__device__ alignas(256) __nv_bfloat16 g_xhb[(size_t)BB*3*KC];      // [context|h] A-side
__device__ alignas(256) __nv_bfloat16 g_hb [(size_t)BB*3*DD];      // h A-side (for ph gemm)
__device__ alignas(256) __nv_bfloat16 g_hsb[(size_t)BB*SS*3*DD];   // hiddens A-side (gen)
__device__ alignas(256) __nv_bfloat16 g_bHb[(size_t)BB*TT*3*DD];   // batch_H A-side (Hp)
__device__ alignas(256) __nv_bfloat16 g_Wcat_b[(size_t)GG*3*KC];   // B-side
__device__ alignas(256) __nv_bfloat16 g_Wi2h_b[(size_t)HH*3*DD];
__device__ alignas(256) __nv_bfloat16 g_Wh2h_b[(size_t)HH*3*DD];
__device__ alignas(256) __nv_bfloat16 g_Wgen_b[(size_t)128*3*DD];  // rows 97..127 zero

// ================= helpers =================
__device__ __forceinline__ uint32_t smem_u32(const void* p) {
    uint32_t a;
    asm("{ .reg .u64 t; cvta.to.shared.u64 t, %1; cvt.u32.u64 %0, t; }" : "=r"(a) : "l"(p));
    return a;
}
__device__ __forceinline__ void ldsm_x4(uint32_t& r0, uint32_t& r1, uint32_t& r2, uint32_t& r3,
                                        uint32_t addr) {
    asm volatile("ldmatrix.sync.aligned.m8n8.x4.shared.b16 {%0,%1,%2,%3}, [%4];"
                 : "=r"(r0), "=r"(r1), "=r"(r2), "=r"(r3) : "r"(addr));
}
__device__ __forceinline__ void mma16816(float* d, uint32_t a0, uint32_t a1, uint32_t a2,
                                         uint32_t a3, uint32_t b0, uint32_t b1) {
    asm volatile(
        "mma.sync.aligned.m16n8k16.row.col.f32.bf16.bf16.f32 "
        "{%0,%1,%2,%3}, {%4,%5,%6,%7}, {%8,%9}, {%0,%1,%2,%3};"
        : "+f"(d[0]), "+f"(d[1]), "+f"(d[2]), "+f"(d[3])
        : "r"(a0), "r"(a1), "r"(a2), "r"(a3), "r"(b0), "r"(b1));
}
__device__ __forceinline__ void cp16(uint32_t dst, const void* src) {
    asm volatile("cp.async.cg.shared.global [%0], [%1], 16;" :: "r"(dst), "l"(src));
}
#define CP_COMMIT asm volatile("cp.async.commit_group;")
#define CP_WAIT1  asm volatile("cp.async.wait_group 1;")

// ================= bf16 K-tripled HMMA GEMM with cp.async pipeline =================
// C[M,N] = A'[M,K3] @ B'[N,K3]^T (+bias); A'/B' are pre-split bf16 triples.
// KIND 0: Hp    M=53248 N=512  K3=1536  (BIG)
// KIND 1: ph    M=2048  N=512  K3=1536  (SMALL 64x64, 128 thr -> 256 CTAs)
// KIND 2: gates M=2048  N=2048 K3=3072  (BIG)
// KIND 3: probs M=65536 N=128pad K3=1536 (BIG, scalar stores to LDC=97)
template<int KIND>
__global__ __launch_bounds__(KIND==1 ? 128 : 256)
void hgemm(const float* __restrict__ bias_in, float* __restrict__ Cout)
{
    constexpr bool BIG = (KIND != 1);
    constexpr int BM = BIG ? 128 : 64;
    constexpr int BNt = BIG ? 128 : 64;
    constexpr int BK = BIG ? 32 : 64;         // bf16 k per chunk
    constexpr int THREADS = BIG ? 256 : 128;
    constexpr int K3 = (KIND==2 ? KC : DD) * 3;
    constexpr int LDC = KIND==2 ? GG : (KIND==3 ? NC : HH);
    constexpr int NCH = K3 / BK;
    constexpr int RSP = BIG ? 40 : 72;        // smem row pitch (bf16)
    constexpr int RSB = RSP * 2;              // bytes
    constexpr int ASTR = BM * RSP;
    constexpr int BSTR = BNt * RSP;
    constexpr int STAGE = ASTR + BSTR;        // bf16 elems per stage
    constexpr int QA = BK / 8;                // 16B granules per row
    constexpr int MF = BIG ? 4 : 2;           // 16-row m frags per warp
    constexpr int NF = 4;                     // 8-col n frags per warp

    extern __shared__ __nv_bfloat16 sm[];
    const int tid = threadIdx.x, wid = tid >> 5, lane = tid & 31;
    const int bm = blockIdx.y * BM, bn = blockIdx.x * BNt;

    const __nv_bfloat16* Aall = KIND==0 ? g_bHb : KIND==1 ? g_hb : KIND==2 ? g_xhb : g_hsb;
    const __nv_bfloat16* Ball = KIND==0 ? g_Wi2h_b : KIND==1 ? g_Wh2h_b
                                : KIND==2 ? g_Wcat_b : g_Wgen_b;
    const float* bias = (KIND==2) ? g_bias : bias_in;
    float* C = KIND==0 ? g_Hp : KIND==1 ? g_ph : KIND==2 ? g_gates : Cout;

    const uint32_t sb = smem_u32(sm);
    const __nv_bfloat16* Ag = Aall + (size_t)bm * K3;
    const __nv_bfloat16* Bg = Ball + (size_t)bn * K3;

    auto issue = [&](int ch, int slot) {
        uint32_t sa = sb + (uint32_t)(slot * STAGE * 2);
        const __nv_bfloat16* ac = Ag + ch * BK;
        #pragma unroll
        for (int i = 0; i < (BM * QA) / THREADS; i++) {
            int idx = tid + i * THREADS;
            int row = idx / QA, q = idx % QA;
            cp16(sa + row * RSB + q * 16, ac + (size_t)row * K3 + q * 8);
        }
        uint32_t sbb = sa + ASTR * 2;
        const __nv_bfloat16* bc = Bg + ch * BK;
        #pragma unroll
        for (int i = 0; i < (BNt * QA) / THREADS; i++) {
            int idx = tid + i * THREADS;
            int row = idx / QA, q = idx % QA;
            cp16(sbb + row * RSB + q * 16, bc + (size_t)row * K3 + q * 8);
        }
        CP_COMMIT;
    };

    const int m_base = (wid & 1) * (BIG ? 64 : 32);
    const int n_base = (wid >> 1) * 32;

    uint32_t aOff[MF], bOff[NF / 2];
    #pragma unroll
    for (int mi = 0; mi < MF; mi++)
        aOff[mi] = (uint32_t)((m_base + mi * 16 + (lane & 15)) * RSB + (lane >> 4) * 16);
    #pragma unroll
    for (int bi = 0; bi < NF / 2; bi++)
        bOff[bi] = (uint32_t)((n_base + bi * 16 + (lane & 15)) * RSB + (lane >> 4) * 16);

    float acc[MF][NF][4];
    #pragma unroll
    for (int mi = 0; mi < MF; mi++)
        #pragma unroll
        for (int ni = 0; ni < NF; ni++)
            #pragma unroll
            for (int i = 0; i < 4; i++) acc[mi][ni][i] = 0.f;

    issue(0, 0);
    issue(1, 1);

    for (int c = 0; c < NCH; c++) {
        const int slot = c % 3;
        CP_WAIT1;
        __syncthreads();
        if (c + 2 < NCH) issue(c + 2, (c + 2) % 3);
        else CP_COMMIT;   // keep group accounting uniform

        const uint32_t ab = sb + (uint32_t)(slot * STAGE * 2);
        const uint32_t bbse = ab + ASTR * 2;
        #pragma unroll
        for (int k16 = 0; k16 < BK / 16; k16++) {
            uint32_t av[MF][4], bv[NF][2];
            #pragma unroll
            for (int mi = 0; mi < MF; mi++)
                ldsm_x4(av[mi][0], av[mi][1], av[mi][2], av[mi][3],
                        ab + aOff[mi] + k16 * 32);
            #pragma unroll
            for (int bi = 0; bi < NF / 2; bi++) {
                uint32_t r0, r1, r2, r3;
                ldsm_x4(r0, r1, r2, r3, bbse + bOff[bi] + k16 * 32);
                bv[bi*2+0][0] = r0; bv[bi*2+0][1] = r2;
                bv[bi*2+1][0] = r1; bv[bi*2+1][1] = r3;
            }
            #pragma unroll
            for (int mi = 0; mi < MF; mi++)
                #pragma unroll
                for (int ni = 0; ni < NF; ni++)
                    mma16816(acc[mi][ni], av[mi][0], av[mi][1], av[mi][2], av[mi][3],
                             bv[ni][0], bv[ni][1]);
        }
    }

    // ---- epilogue ----
    #pragma unroll
    for (int mi = 0; mi < MF; mi++) {
        const int row0 = bm + m_base + mi * 16 + (lane >> 2);
        #pragma unroll
        for (int ni = 0; ni < NF; ni++) {
            const int col = bn + n_base + ni * 8 + (lane & 3) * 2;
            if (KIND != 3) {
                float b0 = 0.f, b1 = 0.f;
                if (KIND != 0) { b0 = bias[col]; b1 = bias[col + 1]; }
                *(float2*)(C + (size_t)row0 * LDC + col) =
                    make_float2(acc[mi][ni][0] + b0, acc[mi][ni][1] + b1);
                *(float2*)(C + (size_t)(row0 + 8) * LDC + col) =
                    make_float2(acc[mi][ni][2] + b0, acc[mi][ni][3] + b1);
            } else {
                #pragma unroll
                for (int h = 0; h < 2; h++) {
                    int cc = col + h;
                    if (cc < NC) {
                        float bb = bias[cc];
                        C[(size_t)row0 * LDC + cc]       = acc[mi][ni][0 + h] + bb;
                        C[(size_t)(row0 + 8) * LDC + cc] = acc[mi][ni][2 + h] + bb;
                    }
                }
            }
        }
    }
}

// ---------------- attention: scores + softmax + context (bf16 triple out) --------
__global__ __launch_bounds__(256) void attn_step(const float* __restrict__ batch_H,
                                                 const float* __restrict__ wscore)
{
    const int b = blockIdx.x;
    const int tid = threadIdx.x;
    const int warp = tid >> 5, lane = tid & 31;
    __shared__ float sph[HH];
    __shared__ float sw[HH];
    __shared__ float se[32];

    const float* ph = g_ph + (size_t)b * HH;
    for (int i = tid; i < HH; i += 256) { sph[i] = ph[i]; sw[i] = wscore[i]; }
    __syncthreads();

    const float* Hpb = g_Hp + (size_t)b * TT * HH;
    for (int t = warp; t < TT; t += 8) {
        const float* hp = Hpb + t * HH;
        float s = 0.f;
        #pragma unroll 4
        for (int k = lane; k < HH; k += 32)
            s += sw[k] * tanhf(hp[k] + sph[k]);
        #pragma unroll
        for (int o = 16; o > 0; o >>= 1) s += __shfl_down_sync(0xffffffffu, s, o);
        if (lane == 0) se[t] = s;
    }
    __syncthreads();

    if (tid < 32) {
        float v = (tid < TT) ? se[tid] : -1e30f;
        float m = v;
        #pragma unroll
        for (int o = 16; o > 0; o >>= 1) m = fmaxf(m, __shfl_xor_sync(0xffffffffu, m, o));
        float ex = (tid < TT) ? __expf(v - m) : 0.f;
        float sum = ex;
        #pragma unroll
        for (int o = 16; o > 0; o >>= 1) sum += __shfl_xor_sync(0xffffffffu, sum, o);
        if (tid < TT) se[tid] = ex / sum;
    }
    __syncthreads();

    const float* bH = batch_H + (size_t)b * TT * DD;
    __nv_bfloat16* xb = g_xhb + (size_t)b * 3 * KC;
    for (int d = tid; d < DD; d += 256) {
        float acc = 0.f;
        #pragma unroll
        for (int t = 0; t < TT; t++)
            acc += se[t] * bH[t * DD + d];
        __nv_bfloat16 hb = __float2bfloat16_rn(acc);
        __nv_bfloat16 lb = __float2bfloat16_rn(acc - __bfloat162float(hb));
        xb[d]            = hb;   // sec0 hi
        xb[KC + d]       = lb;   // sec1 lo
        xb[2 * KC + d]   = hb;   // sec2 hi
    }
}

// ---------------- LSTM pointwise (writes bf16 triples) ----------------------------
__global__ void lstm_pointwise(const int* __restrict__ text, int s)
{
    int idx = blockIdx.x * blockDim.x + threadIdx.x;
    if (idx >= BB * HH) return;
    int b = idx >> 9, j = idx & 511;
    int ch = text[b * SS + s];
    const float* ep = g_embproj + (size_t)ch * GG;
    const float* gr = g_gates + (size_t)b * GG;
    float gi = gr[j]          + ep[j];
    float gf = gr[512 + j]    + ep[512 + j];
    float gg = gr[1024 + j]   + ep[1024 + j];
    float go = gr[1536 + j]   + ep[1536 + j];
    float si = 1.f / (1.f + __expf(-gi));
    float sf = 1.f / (1.f + __expf(-gf));
    float so = 1.f / (1.f + __expf(-go));
    float cn = sf * g_c[idx] + si * tanhf(gg);
    float hn = so * tanhf(cn);
    g_c[idx] = cn;

    __nv_bfloat16 hb = __float2bfloat16_rn(hn);
    __nv_bfloat16 lb = __float2bfloat16_rn(hn - __bfloat162float(hb));
    // gates-GEMM A operand (h at col 512 of each KC-section)
    __nv_bfloat16* xb = g_xhb + (size_t)b * 3 * KC;
    xb[512 + j]          = hb;
    xb[KC + 512 + j]     = lb;
    xb[2 * KC + 512 + j] = hb;
    // ph-GEMM A operand
    __nv_bfloat16* hbp = g_hb + (size_t)b * 3 * DD;
    hbp[j]            = hb;
    hbp[DD + j]       = lb;
    hbp[2 * DD + j]   = hb;
    // generator A operand
    __nv_bfloat16* hs = g_hsb + ((size_t)b * SS + s) * 3 * DD;
    hs[j]           = hb;
    hs[DD + j]      = lb;
    hs[2 * DD + j]  = hb;
}

// ---------------- prep kernels -----------------------------------------------------
__global__ void prep_wcat_b(const float* __restrict__ W_ih, const float* __restrict__ W_hh,
                            const float* __restrict__ b_ih, const float* __restrict__ b_hh)
{
    int idx = blockIdx.x * blockDim.x + threadIdx.x;
    if (idx < GG * KC) {
        int n = idx >> 10, k = idx & 1023;
        float w = (k < 512) ? W_ih[n * 768 + k] : W_hh[n * 512 + k - 512];
        __nv_bfloat16 hb = __float2bfloat16_rn(w);
        __nv_bfloat16 lb = __float2bfloat16_rn(w - __bfloat162float(hb));
        __nv_bfloat16* d = g_Wcat_b + (size_t)n * 3 * KC;
        d[k] = hb; d[KC + k] = hb; d[2 * KC + k] = lb;   // B-side: [hi|hi|lo]
    }
    if (idx < GG) g_bias[idx] = b_ih[idx] + b_hh[idx];
}

template<int W>
__global__ void prep_w512_b(const float* __restrict__ src)
{
    int idx = blockIdx.x * blockDim.x + threadIdx.x;
    if (idx >= HH * DD) return;
    int n = idx >> 9, k = idx & 511;
    float v = src[idx];
    __nv_bfloat16 hb = __float2bfloat16_rn(v);
    __nv_bfloat16 lb = __float2bfloat16_rn(v - __bfloat162float(hb));
    __nv_bfloat16* d = (W == 0 ? g_Wi2h_b : g_Wh2h_b) + (size_t)n * 3 * DD;
    d[k] = hb; d[DD + k] = hb; d[2 * DD + k] = lb;
}

__global__ void prep_wgen_b(const float* __restrict__ W_gen)
{
    int idx = blockIdx.x * blockDim.x + threadIdx.x;
    if (idx >= 128 * DD) return;
    int n = idx >> 9, k = idx & 511;
    float v = (n < NC) ? W_gen[n * DD + k] : 0.f;
    __nv_bfloat16 hb = __float2bfloat16_rn(v);
    __nv_bfloat16 lb = __float2bfloat16_rn(v - __bfloat162float(hb));
    __nv_bfloat16* d = g_Wgen_b + (size_t)n * 3 * DD;
    d[k] = hb; d[DD + k] = hb; d[2 * DD + k] = lb;
}

__global__ void prep_bh_b(const float* __restrict__ batch_H)
{
    int idx = blockIdx.x * blockDim.x + threadIdx.x;
    if (idx >= BB * TT * DD) return;
    int row = idx >> 9, k = idx & 511;
    float v = batch_H[idx];
    __nv_bfloat16 hb = __float2bfloat16_rn(v);
    __nv_bfloat16 lb = __float2bfloat16_rn(v - __bfloat162float(hb));
    __nv_bfloat16* d = g_bHb + (size_t)row * 3 * DD;
    d[k] = hb; d[DD + k] = lb; d[2 * DD + k] = hb;   // A-side: [hi|lo|hi]
}

__global__ void prep_state()
{
    int idx = blockIdx.x * blockDim.x + threadIdx.x;
    if (idx >= BB * HH) return;
    g_c[idx] = 0.f;
    int b = idx >> 9, j = idx & 511;
    __nv_bfloat16 z = __float2bfloat16_rn(0.f);
    __nv_bfloat16* xb = g_xhb + (size_t)b * 3 * KC;
    xb[512 + j] = z; xb[KC + 512 + j] = z; xb[2 * KC + 512 + j] = z;
    __nv_bfloat16* hb = g_hb + (size_t)b * 3 * DD;
    hb[j] = z; hb[DD + j] = z; hb[2 * DD + j] = z;
}

__global__ __launch_bounds__(256) void prep_embproj(const float* __restrict__ emb,
                                                    const float* __restrict__ W_ih)
{
    int c = blockIdx.x;
    __shared__ float s_e[EE];
    for (int i = threadIdx.x; i < EE; i += 256) s_e[i] = emb[c * EE + i];
    __syncthreads();
    for (int n = threadIdx.x; n < GG; n += 256) {
        const float* w = W_ih + (size_t)n * 768 + 512;
        float acc = 0.f;
        #pragma unroll 8
        for (int e = 0; e < EE; e++) acc += s_e[e] * w[e];
        g_embproj[(size_t)c * GG + n] = acc;
    }
}

// ---------------- launch -----------------------------------------------------------
extern "C" void kernel_launch(void* const* d_in, const int* in_sizes, int n_in,
                              void* d_out, int out_size)
{
    const float* batch_H  = (const float*)d_in[0];
    const int*   text     = (const int*)  d_in[1];
    const float* W_i2h    = (const float*)d_in[2];
    const float* W_h2h    = (const float*)d_in[3];
    const float* b_h2h    = (const float*)d_in[4];
    const float* w_score  = (const float*)d_in[5];
    const float* W_ih     = (const float*)d_in[6];
    const float* W_hh     = (const float*)d_in[7];
    const float* b_ih     = (const float*)d_in[8];
    const float* b_hh     = (const float*)d_in[9];
    const float* W_gen    = (const float*)d_in[10];
    const float* b_gen    = (const float*)d_in[11];
    const float* emb      = (const float*)d_in[12];
    float* out = (float*)d_out;

    const int smemBIG   = 3 * (128 + 128) * 40 * 2;   // 61440
    const int smemSMALL = 3 * (64 + 64) * 72 * 2;     // 55296
    cudaFuncSetAttribute(hgemm<0>, cudaFuncAttributeMaxDynamicSharedMemorySize, smemBIG);
    cudaFuncSetAttribute(hgemm<1>, cudaFuncAttributeMaxDynamicSharedMemorySize, smemSMALL);
    cudaFuncSetAttribute(hgemm<2>, cudaFuncAttributeMaxDynamicSharedMemorySize, smemBIG);
    cudaFuncSetAttribute(hgemm<3>, cudaFuncAttributeMaxDynamicSharedMemorySize, smemBIG);

    // prologue: weight/activation splitting + state init
    prep_wcat_b<<<(GG * KC + 255) / 256, 256>>>(W_ih, W_hh, b_ih, b_hh);
    prep_w512_b<0><<<(HH * DD + 255) / 256, 256>>>(W_i2h);
    prep_w512_b<1><<<(HH * DD + 255) / 256, 256>>>(W_h2h);
    prep_wgen_b<<<(128 * DD + 255) / 256, 256>>>(W_gen);
    prep_bh_b<<<(BB * TT * DD + 255) / 256, 256>>>(batch_H);
    prep_state<<<(BB * HH + 255) / 256, 256>>>();
    prep_embproj<<<NC, 256>>>(emb, W_ih);

    // Hp = batch_H @ W_i2h^T
    hgemm<0><<<dim3(HH / 128, (BB * TT) / 128), 256, smemBIG>>>(nullptr, nullptr);

    // 32 decode steps
    for (int s = 0; s < SS; s++) {
        hgemm<1><<<dim3(HH / 64, BB / 64), 128, smemSMALL>>>(b_h2h, nullptr);
        attn_step<<<BB, 256>>>(batch_H, w_score);
        hgemm<2><<<dim3(GG / 128, BB / 128), 256, smemBIG>>>(nullptr, nullptr);
        lstm_pointwise<<<(BB * HH + 255) / 256, 256>>>(text, s);
    }

    // probs = hs @ W_gen^T + b_gen
    hgemm<3><<<dim3(1, (BB * SS) / 128), 256, smemBIG>>>(b_gen, out);
}

// round 6
// speedup vs baseline: 1.1658x; 1.1658x over previous
#include <cuda_runtime.h>
#include <cuda_bf16.h>
#include <cstdint>

#define BB 2048
#define TT 26
#define DD 512
#define HH 512
#define EE 256
#define NC 97
#define SS 32
#define GG 2048   // 4*H
#define KC 1024   // concat K = D + H

// ---------------- scratch (static device memory; no allocations) ----------------
__device__ alignas(256) float g_Hp[(size_t)BB*TT*HH];
__device__ alignas(256) float g_c[(size_t)BB*HH];
__device__ alignas(256) float g_ph[(size_t)BB*HH];
__device__ alignas(256) float g_gates[(size_t)BB*GG];
__device__ alignas(256) float g_bias[GG];
__device__ alignas(256) float g_embproj[(size_t)NC*GG];
// pre-split bf16 hi/lo planes (x = hi + lo)
__device__ alignas(256) __nv_bfloat16 g_xh_h[(size_t)BB*KC], g_xh_l[(size_t)BB*KC];
__device__ alignas(256) __nv_bfloat16 g_h_h [(size_t)BB*DD], g_h_l [(size_t)BB*DD];
__device__ alignas(256) __nv_bfloat16 g_hs_h[(size_t)BB*SS*DD], g_hs_l[(size_t)BB*SS*DD];
__device__ alignas(256) __nv_bfloat16 g_bH_h[(size_t)BB*TT*DD], g_bH_l[(size_t)BB*TT*DD];
__device__ alignas(256) __nv_bfloat16 g_Wcat_h[(size_t)GG*KC], g_Wcat_l[(size_t)GG*KC];
__device__ alignas(256) __nv_bfloat16 g_Wi2h_h[(size_t)HH*DD], g_Wi2h_l[(size_t)HH*DD];
__device__ alignas(256) __nv_bfloat16 g_Wh2h_h[(size_t)HH*DD], g_Wh2h_l[(size_t)HH*DD];
__device__ alignas(256) __nv_bfloat16 g_Wgen_h[(size_t)128*DD], g_Wgen_l[(size_t)128*DD];

// ================= helpers =================
__device__ __forceinline__ uint32_t smem_u32(const void* p) {
    uint32_t a;
    asm("{ .reg .u64 t; cvta.to.shared.u64 t, %1; cvt.u32.u64 %0, t; }" : "=r"(a) : "l"(p));
    return a;
}
__device__ __forceinline__ void ldsm_x4(uint32_t& r0, uint32_t& r1, uint32_t& r2, uint32_t& r3,
                                        uint32_t addr) {
    asm volatile("ldmatrix.sync.aligned.m8n8.x4.shared.b16 {%0,%1,%2,%3}, [%4];"
                 : "=r"(r0), "=r"(r1), "=r"(r2), "=r"(r3) : "r"(addr));
}
__device__ __forceinline__ void mma16816(float* d, const uint32_t* a, const uint32_t* b) {
    asm volatile(
        "mma.sync.aligned.m16n8k16.row.col.f32.bf16.bf16.f32 "
        "{%0,%1,%2,%3}, {%4,%5,%6,%7}, {%8,%9}, {%0,%1,%2,%3};"
        : "+f"(d[0]), "+f"(d[1]), "+f"(d[2]), "+f"(d[3])
        : "r"(a[0]), "r"(a[1]), "r"(a[2]), "r"(a[3]), "r"(b[0]), "r"(b[1]));
}
__device__ __forceinline__ void cp16(uint32_t dst, const void* src) {
    asm volatile("cp.async.cg.shared.global [%0], [%1], 16;" :: "r"(dst), "l"(src));
}
#define CP_COMMIT asm volatile("cp.async.commit_group;")
#define CP_WAIT1  asm volatile("cp.async.wait_group 1;")
__device__ __forceinline__ float tanh_fast(float x) {
    float r;
    asm("tanh.approx.f32 %0, %1;" : "=f"(r) : "f"(x));
    return r;
}
__device__ __forceinline__ void split2(float x, __nv_bfloat16& h, __nv_bfloat16& l) {
    h = __float2bfloat16_rn(x);
    l = __float2bfloat16_rn(x - __bfloat162float(h));
}

// ================= hi/lo-plane bf16 HMMA GEMM, 3-term split ======================
// C[M,N] = (Ah+Al)[M,K] @ (Bh+Bl)[N,K]^T (+bias), terms AhBh + AlBh + AhBl.
// 3-stage cp.async pipeline; smem pitch 80B (conflict-free ldmatrix).
template<int BM, int BN, int WM, int WN, int TH, int K, int LDC, bool BIAS, bool NT97>
__global__ __launch_bounds__(TH, 1)
void hgemm(const __nv_bfloat16* __restrict__ Ah, const __nv_bfloat16* __restrict__ Al,
           const __nv_bfloat16* __restrict__ Bh, const __nv_bfloat16* __restrict__ Bl,
           const float* __restrict__ bias, float* __restrict__ C)
{
    constexpr int NCH = K / 32;
    constexpr int MF = WM / 16;         // 16-row m frags per warp
    constexpr int NF = WN / 8;          // 8-col n frags
    constexpr int NFB = WN / 16;        // ldsm groups for B
    constexpr int NWN = BN / WN;        // warps along n
    constexpr int OF_AL = BM * 80;
    constexpr int OF_BH = 2 * BM * 80;
    constexpr int OF_BL = 2 * BM * 80 + BN * 80;
    constexpr int STAGEB = 2 * (BM + BN) * 80;

    extern __shared__ char smc[];
    const int tid = threadIdx.x, wid = tid >> 5, lane = tid & 31;
    const int bm = blockIdx.y * BM, bn = blockIdx.x * BN;
    const uint32_t sb = smem_u32(smc);

    const __nv_bfloat16* Ahg = Ah + (size_t)bm * K;
    const __nv_bfloat16* Alg = Al + (size_t)bm * K;
    const __nv_bfloat16* Bhg = Bh + (size_t)bn * K;
    const __nv_bfloat16* Blg = Bl + (size_t)bn * K;

    auto issue = [&](int ch, int slot) {
        const uint32_t st = sb + (uint32_t)(slot * STAGEB);
        const int kof = ch * 32;
        #pragma unroll
        for (int i = 0; i < (BM * 4) / TH; i++) {
            int idx = tid + i * TH, row = idx >> 2, q = idx & 3;
            cp16(st + row * 80 + q * 16, Ahg + (size_t)row * K + kof + q * 8);
        }
        #pragma unroll
        for (int i = 0; i < (BM * 4) / TH; i++) {
            int idx = tid + i * TH, row = idx >> 2, q = idx & 3;
            cp16(st + OF_AL + row * 80 + q * 16, Alg + (size_t)row * K + kof + q * 8);
        }
        #pragma unroll
        for (int i = 0; i < (BN * 4) / TH; i++) {
            int idx = tid + i * TH, row = idx >> 2, q = idx & 3;
            cp16(st + OF_BH + row * 80 + q * 16, Bhg + (size_t)row * K + kof + q * 8);
        }
        #pragma unroll
        for (int i = 0; i < (BN * 4) / TH; i++) {
            int idx = tid + i * TH, row = idx >> 2, q = idx & 3;
            cp16(st + OF_BL + row * 80 + q * 16, Blg + (size_t)row * K + kof + q * 8);
        }
        CP_COMMIT;
    };

    const int m_base = (wid / NWN) * WM;
    const int n_base = (wid % NWN) * WN;

    uint32_t aOff[MF], bOff[NFB];
    #pragma unroll
    for (int mi = 0; mi < MF; mi++)
        aOff[mi] = (uint32_t)((m_base + mi * 16 + (lane & 15)) * 80 + (lane >> 4) * 16);
    #pragma unroll
    for (int bi = 0; bi < NFB; bi++)
        bOff[bi] = (uint32_t)((n_base + bi * 16 + (lane & 15)) * 80 + (lane >> 4) * 16);

    float acc[MF][NF][4];
    #pragma unroll
    for (int mi = 0; mi < MF; mi++)
        #pragma unroll
        for (int ni = 0; ni < NF; ni++)
            #pragma unroll
            for (int i = 0; i < 4; i++) acc[mi][ni][i] = 0.f;

    issue(0, 0);
    issue(1, 1);

    for (int c = 0; c < NCH; c++) {
        const int slot = c % 3;
        CP_WAIT1;
        __syncthreads();
        if (c + 2 < NCH) issue(c + 2, (c + 2) % 3);
        else CP_COMMIT;   // keep group count uniform

        const uint32_t st = sb + (uint32_t)(slot * STAGEB);
        #pragma unroll
        for (int k16 = 0; k16 < 2; k16++) {
            const uint32_t ko = k16 * 32;
            uint32_t bh[NF][2], bl[NF][2];
            #pragma unroll
            for (int bi = 0; bi < NFB; bi++) {
                uint32_t r0, r1, r2, r3;
                ldsm_x4(r0, r1, r2, r3, st + OF_BH + bOff[bi] + ko);
                bh[bi*2+0][0] = r0; bh[bi*2+0][1] = r2;
                bh[bi*2+1][0] = r1; bh[bi*2+1][1] = r3;
                ldsm_x4(r0, r1, r2, r3, st + OF_BL + bOff[bi] + ko);
                bl[bi*2+0][0] = r0; bl[bi*2+0][1] = r2;
                bl[bi*2+1][0] = r1; bl[bi*2+1][1] = r3;
            }
            #pragma unroll
            for (int mi = 0; mi < MF; mi++) {
                uint32_t ah[4], al[4];
                ldsm_x4(ah[0], ah[1], ah[2], ah[3], st + aOff[mi] + ko);
                ldsm_x4(al[0], al[1], al[2], al[3], st + OF_AL + aOff[mi] + ko);
                #pragma unroll
                for (int ni = 0; ni < NF; ni++) {
                    mma16816(acc[mi][ni], ah, bh[ni]);
                    mma16816(acc[mi][ni], al, bh[ni]);
                    mma16816(acc[mi][ni], ah, bl[ni]);
                }
            }
        }
    }

    // ---- epilogue ----
    #pragma unroll
    for (int mi = 0; mi < MF; mi++) {
        const int row0 = bm + m_base + mi * 16 + (lane >> 2);
        #pragma unroll
        for (int ni = 0; ni < NF; ni++) {
            const int col = bn + n_base + ni * 8 + (lane & 3) * 2;
            if (!NT97) {
                float b0 = 0.f, b1 = 0.f;
                if (BIAS) { b0 = bias[col]; b1 = bias[col + 1]; }
                *(float2*)(C + (size_t)row0 * LDC + col) =
                    make_float2(acc[mi][ni][0] + b0, acc[mi][ni][1] + b1);
                *(float2*)(C + (size_t)(row0 + 8) * LDC + col) =
                    make_float2(acc[mi][ni][2] + b0, acc[mi][ni][3] + b1);
            } else {
                #pragma unroll
                for (int h = 0; h < 2; h++) {
                    int cc = col + h;
                    if (cc < NC) {
                        float bb = BIAS ? bias[cc] : 0.f;
                        C[(size_t)row0 * LDC + cc]       = acc[mi][ni][0 + h] + bb;
                        C[(size_t)(row0 + 8) * LDC + cc] = acc[mi][ni][2 + h] + bb;
                    }
                }
            }
        }
    }
}

// ---------------- attention: scores + softmax + context ---------------------------
__global__ __launch_bounds__(256) void attn_step(const float* __restrict__ batch_H,
                                                 const float* __restrict__ wscore)
{
    const int b = blockIdx.x;
    const int tid = threadIdx.x;
    const int warp = tid >> 5, lane = tid & 31;
    __shared__ float sph[HH];
    __shared__ float sw[HH];
    __shared__ float se[32];

    const float* ph = g_ph + (size_t)b * HH;
    for (int i = tid; i < HH; i += 256) { sph[i] = ph[i]; sw[i] = wscore[i]; }
    __syncthreads();

    const float* Hpb = g_Hp + (size_t)b * TT * HH;
    for (int t = warp; t < TT; t += 8) {
        const float* hp = Hpb + t * HH;
        float s = 0.f;
        #pragma unroll 4
        for (int k = lane; k < HH; k += 32)
            s += sw[k] * tanh_fast(hp[k] + sph[k]);
        #pragma unroll
        for (int o = 16; o > 0; o >>= 1) s += __shfl_down_sync(0xffffffffu, s, o);
        if (lane == 0) se[t] = s;
    }
    __syncthreads();

    if (tid < 32) {
        float v = (tid < TT) ? se[tid] : -1e30f;
        float m = v;
        #pragma unroll
        for (int o = 16; o > 0; o >>= 1) m = fmaxf(m, __shfl_xor_sync(0xffffffffu, m, o));
        float ex = (tid < TT) ? __expf(v - m) : 0.f;
        float sum = ex;
        #pragma unroll
        for (int o = 16; o > 0; o >>= 1) sum += __shfl_xor_sync(0xffffffffu, sum, o);
        if (tid < TT) se[tid] = ex / sum;
    }
    __syncthreads();

    const float* bH = batch_H + (size_t)b * TT * DD;
    for (int d = tid; d < DD; d += 256) {
        float acc = 0.f;
        #pragma unroll
        for (int t = 0; t < TT; t++)
            acc += se[t] * bH[t * DD + d];
        __nv_bfloat16 h, l;
        split2(acc, h, l);
        g_xh_h[(size_t)b * KC + d] = h;
        g_xh_l[(size_t)b * KC + d] = l;
    }
}

// ---------------- LSTM pointwise ---------------------------------------------------
__global__ void lstm_pointwise(const int* __restrict__ text, int s)
{
    int idx = blockIdx.x * blockDim.x + threadIdx.x;
    if (idx >= BB * HH) return;
    int b = idx >> 9, j = idx & 511;
    int ch = text[b * SS + s];
    const float* ep = g_embproj + (size_t)ch * GG;
    const float* gr = g_gates + (size_t)b * GG;
    float gi = gr[j]          + ep[j];
    float gf = gr[512 + j]    + ep[512 + j];
    float gg = gr[1024 + j]   + ep[1024 + j];
    float go = gr[1536 + j]   + ep[1536 + j];
    float si = 1.f / (1.f + __expf(-gi));
    float sf = 1.f / (1.f + __expf(-gf));
    float so = 1.f / (1.f + __expf(-go));
    float cn = sf * g_c[idx] + si * tanhf(gg);
    float hn = so * tanhf(cn);
    g_c[idx] = cn;

    __nv_bfloat16 h, l;
    split2(hn, h, l);
    g_xh_h[(size_t)b * KC + 512 + j] = h;
    g_xh_l[(size_t)b * KC + 512 + j] = l;
    g_h_h[idx] = h;
    g_h_l[idx] = l;
    size_t hsoff = ((size_t)b * SS + s) * DD + j;
    g_hs_h[hsoff] = h;
    g_hs_l[hsoff] = l;
}

// ---------------- prep kernels -------------------------------------------------------
__global__ void prep_wcat(const float* __restrict__ W_ih, const float* __restrict__ W_hh,
                          const float* __restrict__ b_ih, const float* __restrict__ b_hh)
{
    int idx = blockIdx.x * blockDim.x + threadIdx.x;
    if (idx < GG * KC) {
        int n = idx >> 10, k = idx & 1023;
        float w = (k < 512) ? W_ih[n * 768 + k] : W_hh[n * 512 + k - 512];
        __nv_bfloat16 h, l; split2(w, h, l);
        g_Wcat_h[idx] = h; g_Wcat_l[idx] = l;
    }
    if (idx < GG) g_bias[idx] = b_ih[idx] + b_hh[idx];
}

template<int W>
__global__ void prep_w512(const float* __restrict__ src)
{
    int idx = blockIdx.x * blockDim.x + threadIdx.x;
    if (idx >= HH * DD) return;
    float v = src[idx];
    __nv_bfloat16 h, l; split2(v, h, l);
    if (W == 0) { g_Wi2h_h[idx] = h; g_Wi2h_l[idx] = l; }
    else        { g_Wh2h_h[idx] = h; g_Wh2h_l[idx] = l; }
}

__global__ void prep_wgen(const float* __restrict__ W_gen)
{
    int idx = blockIdx.x * blockDim.x + threadIdx.x;
    if (idx >= 128 * DD) return;
    int n = idx >> 9;
    float v = (n < NC) ? W_gen[(size_t)n * DD + (idx & 511)] : 0.f;
    __nv_bfloat16 h, l; split2(v, h, l);
    g_Wgen_h[idx] = h; g_Wgen_l[idx] = l;
}

__global__ void prep_bh(const float* __restrict__ batch_H)
{
    int idx = blockIdx.x * blockDim.x + threadIdx.x;
    if (idx >= BB * TT * DD) return;
    float v = batch_H[idx];
    __nv_bfloat16 h, l; split2(v, h, l);
    g_bH_h[idx] = h; g_bH_l[idx] = l;
}

__global__ void prep_state()
{
    int idx = blockIdx.x * blockDim.x + threadIdx.x;
    if (idx >= BB * HH) return;
    g_c[idx] = 0.f;
    int b = idx >> 9, j = idx & 511;
    __nv_bfloat16 z = __float2bfloat16_rn(0.f);
    g_xh_h[(size_t)b * KC + 512 + j] = z;
    g_xh_l[(size_t)b * KC + 512 + j] = z;
    g_h_h[idx] = z; g_h_l[idx] = z;
}

__global__ __launch_bounds__(256) void prep_embproj(const float* __restrict__ emb,
                                                    const float* __restrict__ W_ih)
{
    int c = blockIdx.x;
    __shared__ float s_e[EE];
    for (int i = threadIdx.x; i < EE; i += 256) s_e[i] = emb[c * EE + i];
    __syncthreads();
    for (int n = threadIdx.x; n < GG; n += 256) {
        const float* w = W_ih + (size_t)n * 768 + 512;
        float acc = 0.f;
        #pragma unroll 8
        for (int e = 0; e < EE; e++) acc += s_e[e] * w[e];
        g_embproj[(size_t)c * GG + n] = acc;
    }
}

// ---------------- launch --------------------------------------------------------------
extern "C" void kernel_launch(void* const* d_in, const int* in_sizes, int n_in,
                              void* d_out, int out_size)
{
    const float* batch_H  = (const float*)d_in[0];
    const int*   text     = (const int*)  d_in[1];
    const float* W_i2h    = (const float*)d_in[2];
    const float* W_h2h    = (const float*)d_in[3];
    const float* b_h2h    = (const float*)d_in[4];
    const float* w_score  = (const float*)d_in[5];
    const float* W_ih     = (const float*)d_in[6];
    const float* W_hh     = (const float*)d_in[7];
    const float* b_ih     = (const float*)d_in[8];
    const float* b_hh     = (const float*)d_in[9];
    const float* W_gen    = (const float*)d_in[10];
    const float* b_gen    = (const float*)d_in[11];
    const float* emb      = (const float*)d_in[12];
    float* out = (float*)d_out;

    // resolve device-symbol addresses (host side, graph-safe)
    static __nv_bfloat16 *p_xh_h, *p_xh_l, *p_h_h, *p_h_l, *p_hs_h, *p_hs_l,
                         *p_bH_h, *p_bH_l, *p_Wc_h, *p_Wc_l, *p_Wi_h, *p_Wi_l,
                         *p_Wh_h, *p_Wh_l, *p_Wg_h, *p_Wg_l;
    static float *p_Hp, *p_ph, *p_gates, *p_bias;
    static bool init = false;
    if (!init) {
        cudaGetSymbolAddress((void**)&p_xh_h, g_xh_h);
        cudaGetSymbolAddress((void**)&p_xh_l, g_xh_l);
        cudaGetSymbolAddress((void**)&p_h_h,  g_h_h);
        cudaGetSymbolAddress((void**)&p_h_l,  g_h_l);
        cudaGetSymbolAddress((void**)&p_hs_h, g_hs_h);
        cudaGetSymbolAddress((void**)&p_hs_l, g_hs_l);
        cudaGetSymbolAddress((void**)&p_bH_h, g_bH_h);
        cudaGetSymbolAddress((void**)&p_bH_l, g_bH_l);
        cudaGetSymbolAddress((void**)&p_Wc_h, g_Wcat_h);
        cudaGetSymbolAddress((void**)&p_Wc_l, g_Wcat_l);
        cudaGetSymbolAddress((void**)&p_Wi_h, g_Wi2h_h);
        cudaGetSymbolAddress((void**)&p_Wi_l, g_Wi2h_l);
        cudaGetSymbolAddress((void**)&p_Wh_h, g_Wh2h_h);
        cudaGetSymbolAddress((void**)&p_Wh_l, g_Wh2h_l);
        cudaGetSymbolAddress((void**)&p_Wg_h, g_Wgen_h);
        cudaGetSymbolAddress((void**)&p_Wg_l, g_Wgen_l);
        cudaGetSymbolAddress((void**)&p_Hp,    g_Hp);
        cudaGetSymbolAddress((void**)&p_ph,    g_ph);
        cudaGetSymbolAddress((void**)&p_gates, g_gates);
        cudaGetSymbolAddress((void**)&p_bias,  g_bias);
        init = true;
    }

    // hgemm instantiations
    auto kHp    = hgemm<128,256,64,64,256, DD, HH, false,false>;
    auto kPh    = hgemm< 64,128,32,64,128, DD, HH, true, false>;
    auto kGates = hgemm<128,256,64,64,256, KC, GG, true, false>;
    auto kGen   = hgemm<128,128,64,32,256, DD, NC, true, true >;

    const int smHp    = 3 * 2 * (128 + 256) * 80;   // 184320
    const int smPh    = 3 * 2 * ( 64 + 128) * 80;   // 92160
    const int smGates = smHp;
    const int smGen   = 3 * 2 * (128 + 128) * 80;   // 122880
    cudaFuncSetAttribute(kHp,    cudaFuncAttributeMaxDynamicSharedMemorySize, smHp);
    cudaFuncSetAttribute(kPh,    cudaFuncAttributeMaxDynamicSharedMemorySize, smPh);
    cudaFuncSetAttribute(kGates, cudaFuncAttributeMaxDynamicSharedMemorySize, smGates);
    cudaFuncSetAttribute(kGen,   cudaFuncAttributeMaxDynamicSharedMemorySize, smGen);

    // prologue
    prep_wcat<<<(GG * KC + 255) / 256, 256>>>(W_ih, W_hh, b_ih, b_hh);
    prep_w512<0><<<(HH * DD + 255) / 256, 256>>>(W_i2h);
    prep_w512<1><<<(HH * DD + 255) / 256, 256>>>(W_h2h);
    prep_wgen<<<(128 * DD + 255) / 256, 256>>>(W_gen);
    prep_bh<<<(BB * TT * DD + 255) / 256, 256>>>(batch_H);
    prep_state<<<(BB * HH + 255) / 256, 256>>>();
    prep_embproj<<<NC, 256>>>(emb, W_ih);

    // Hp = batch_H @ W_i2h^T
    kHp<<<dim3(HH/256, (BB*TT)/128), 256, smHp>>>(p_bH_h, p_bH_l, p_Wi_h, p_Wi_l,
                                                  nullptr, p_Hp);

    // 32 decode steps
    for (int s = 0; s < SS; s++) {
        kPh<<<dim3(HH/128, BB/64), 128, smPh>>>(p_h_h, p_h_l, p_Wh_h, p_Wh_l,
                                                b_h2h, p_ph);
        attn_step<<<BB, 256>>>(batch_H, w_score);
        kGates<<<dim3(GG/256, BB/128), 256, smGates>>>(p_xh_h, p_xh_l, p_Wc_h, p_Wc_l,
                                                       p_bias, p_gates);
        lstm_pointwise<<<(BB * HH + 255) / 256, 256>>>(text, s);
    }

    // probs = hs @ W_gen^T + b_gen
    kGen<<<dim3(1, (BB*SS)/128), 256, smGen>>>(p_hs_h, p_hs_l, p_Wg_h, p_Wg_l,
                                               b_gen, out);
}

// round 7
// speedup vs baseline: 1.2223x; 1.0485x over previous
#include <cuda_runtime.h>
#include <cuda_bf16.h>
#include <cuda_fp16.h>
#include <cstdint>

#define BB 2048
#define TT 26
#define DD 512
#define HH 512
#define EE 256
#define NC 97
#define SS 32
#define GG 2048   // 4*H
#define KC 1024   // concat K = D + H

// ---------------- scratch (static device memory; no allocations) ----------------
__device__ alignas(256) float g_c[(size_t)BB*HH];
__device__ alignas(256) float g_ph[(size_t)BB*HH];
__device__ alignas(256) float g_ep[(size_t)NC*GG];            // permuted embproj + bias
__device__ alignas(256) __half g_Hp16[(size_t)BB*TT*HH];
__device__ alignas(256) __half g_bH16[(size_t)BB*TT*DD];
// pre-split bf16 hi/lo planes (x = hi + lo)
__device__ alignas(256) __nv_bfloat16 g_xh_h[(size_t)BB*KC], g_xh_l[(size_t)BB*KC];
__device__ alignas(256) __nv_bfloat16 g_h_h [(size_t)BB*DD], g_h_l [(size_t)BB*DD];
__device__ alignas(256) __nv_bfloat16 g_hs_h[(size_t)BB*SS*DD], g_hs_l[(size_t)BB*SS*DD];
__device__ alignas(256) __nv_bfloat16 g_bH_h[(size_t)BB*TT*DD], g_bH_l[(size_t)BB*TT*DD];
__device__ alignas(256) __nv_bfloat16 g_Wcat_h[(size_t)GG*KC], g_Wcat_l[(size_t)GG*KC]; // PERMUTED
__device__ alignas(256) __nv_bfloat16 g_Wi2h_h[(size_t)HH*DD], g_Wi2h_l[(size_t)HH*DD];
__device__ alignas(256) __nv_bfloat16 g_Wh2h_h[(size_t)HH*DD], g_Wh2h_l[(size_t)HH*DD];
__device__ alignas(256) __nv_bfloat16 g_Wgen_h[(size_t)128*DD], g_Wgen_l[(size_t)128*DD];

// gate-interleave permutation: physical col p <-> (gate g, unit u)
// p = w*64 + (4r+g)*8 + q*2 + e ;  u = w*16 + r*8 + q*2 + e
__device__ __host__ __forceinline__ int perm_orig_row(int p) {
    int w = p >> 6, m = p & 63;
    int ni = m >> 3, r = ni >> 2, g = ni & 3;
    int q = (m >> 1) & 3, e = m & 1;
    int u = w * 16 + r * 8 + q * 2 + e;
    return g * 512 + u;
}

// ================= helpers =================
__device__ __forceinline__ uint32_t smem_u32(const void* p) {
    uint32_t a;
    asm("{ .reg .u64 t; cvta.to.shared.u64 t, %1; cvt.u32.u64 %0, t; }" : "=r"(a) : "l"(p));
    return a;
}
__device__ __forceinline__ void ldsm_x4(uint32_t& r0, uint32_t& r1, uint32_t& r2, uint32_t& r3,
                                        uint32_t addr) {
    asm volatile("ldmatrix.sync.aligned.m8n8.x4.shared.b16 {%0,%1,%2,%3}, [%4];"
                 : "=r"(r0), "=r"(r1), "=r"(r2), "=r"(r3) : "r"(addr));
}
__device__ __forceinline__ void mma16816(float* d, const uint32_t* a, const uint32_t* b) {
    asm volatile(
        "mma.sync.aligned.m16n8k16.row.col.f32.bf16.bf16.f32 "
        "{%0,%1,%2,%3}, {%4,%5,%6,%7}, {%8,%9}, {%0,%1,%2,%3};"
        : "+f"(d[0]), "+f"(d[1]), "+f"(d[2]), "+f"(d[3])
        : "r"(a[0]), "r"(a[1]), "r"(a[2]), "r"(a[3]), "r"(b[0]), "r"(b[1]));
}
__device__ __forceinline__ void cp16(uint32_t dst, const void* src) {
    asm volatile("cp.async.cg.shared.global [%0], [%1], 16;" :: "r"(dst), "l"(src));
}
#define CP_COMMIT asm volatile("cp.async.commit_group;")
#define CP_WAIT1  asm volatile("cp.async.wait_group 1;")
__device__ __forceinline__ float tanh_fast(float x) {
    float r;
    asm("tanh.approx.f32 %0, %1;" : "=f"(r) : "f"(x));
    return r;
}
__device__ __forceinline__ void split2(float x, __nv_bfloat16& h, __nv_bfloat16& l) {
    h = __float2bfloat16_rn(x);
    l = __float2bfloat16_rn(x - __bfloat162float(h));
}

// ================= hi/lo-plane bf16 HMMA GEMM, 3-term split ======================
// MODE 1: fp32 out + bias (ph)
// MODE 2: fp32 out + bias, N=97 tail, scalar stores (generator)
// MODE 3: fp16 out, no bias (Hp)
// MODE 4: fused LSTM epilogue (gates; C unused, writes h/c/planes)
template<int BM, int BN, int WM, int WN, int TH, int K, int LDC, int MODE>
__global__ __launch_bounds__(TH, 1)
void hgemm(const __nv_bfloat16* __restrict__ Ah, const __nv_bfloat16* __restrict__ Al,
           const __nv_bfloat16* __restrict__ Bh, const __nv_bfloat16* __restrict__ Bl,
           const float* __restrict__ bias, float* __restrict__ C,
           __half* __restrict__ C16, const int* __restrict__ text, int s)
{
    constexpr int NCH = K / 32;
    constexpr int MF = WM / 16;
    constexpr int NF = WN / 8;
    constexpr int NFB = WN / 16;
    constexpr int NWN = BN / WN;
    constexpr int OF_AL = BM * 80;
    constexpr int OF_BH = 2 * BM * 80;
    constexpr int OF_BL = 2 * BM * 80 + BN * 80;
    constexpr int STAGEB = 2 * (BM + BN) * 80;

    extern __shared__ char smc[];
    const int tid = threadIdx.x, wid = tid >> 5, lane = tid & 31;
    const int bm = blockIdx.y * BM, bn = blockIdx.x * BN;
    const uint32_t sb = smem_u32(smc);

    const __nv_bfloat16* Ahg = Ah + (size_t)bm * K;
    const __nv_bfloat16* Alg = Al + (size_t)bm * K;
    const __nv_bfloat16* Bhg = Bh + (size_t)bn * K;
    const __nv_bfloat16* Blg = Bl + (size_t)bn * K;

    auto issue = [&](int ch, int slot) {
        const uint32_t st = sb + (uint32_t)(slot * STAGEB);
        const int kof = ch * 32;
        #pragma unroll
        for (int i = 0; i < (BM * 4) / TH; i++) {
            int idx = tid + i * TH, row = idx >> 2, q = idx & 3;
            cp16(st + row * 80 + q * 16, Ahg + (size_t)row * K + kof + q * 8);
        }
        #pragma unroll
        for (int i = 0; i < (BM * 4) / TH; i++) {
            int idx = tid + i * TH, row = idx >> 2, q = idx & 3;
            cp16(st + OF_AL + row * 80 + q * 16, Alg + (size_t)row * K + kof + q * 8);
        }
        #pragma unroll
        for (int i = 0; i < (BN * 4) / TH; i++) {
            int idx = tid + i * TH, row = idx >> 2, q = idx & 3;
            cp16(st + OF_BH + row * 80 + q * 16, Bhg + (size_t)row * K + kof + q * 8);
        }
        #pragma unroll
        for (int i = 0; i < (BN * 4) / TH; i++) {
            int idx = tid + i * TH, row = idx >> 2, q = idx & 3;
            cp16(st + OF_BL + row * 80 + q * 16, Blg + (size_t)row * K + kof + q * 8);
        }
        CP_COMMIT;
    };

    const int m_base = (wid / NWN) * WM;
    const int n_base = (wid % NWN) * WN;

    uint32_t aOff[MF], bOff[NFB];
    #pragma unroll
    for (int mi = 0; mi < MF; mi++)
        aOff[mi] = (uint32_t)((m_base + mi * 16 + (lane & 15)) * 80 + (lane >> 4) * 16);
    #pragma unroll
    for (int bi = 0; bi < NFB; bi++)
        bOff[bi] = (uint32_t)((n_base + bi * 16 + (lane & 15)) * 80 + (lane >> 4) * 16);

    float acc[MF][NF][4];
    #pragma unroll
    for (int mi = 0; mi < MF; mi++)
        #pragma unroll
        for (int ni = 0; ni < NF; ni++)
            #pragma unroll
            for (int i = 0; i < 4; i++) acc[mi][ni][i] = 0.f;

    issue(0, 0);
    issue(1, 1);

    for (int c = 0; c < NCH; c++) {
        const int slot = c % 3;
        CP_WAIT1;
        __syncthreads();
        if (c + 2 < NCH) issue(c + 2, (c + 2) % 3);
        else CP_COMMIT;

        const uint32_t st = sb + (uint32_t)(slot * STAGEB);
        #pragma unroll
        for (int k16 = 0; k16 < 2; k16++) {
            const uint32_t ko = k16 * 32;
            uint32_t bh[NF][2], bl[NF][2];
            #pragma unroll
            for (int bi = 0; bi < NFB; bi++) {
                uint32_t r0, r1, r2, r3;
                ldsm_x4(r0, r1, r2, r3, st + OF_BH + bOff[bi] + ko);
                bh[bi*2+0][0] = r0; bh[bi*2+0][1] = r2;
                bh[bi*2+1][0] = r1; bh[bi*2+1][1] = r3;
                ldsm_x4(r0, r1, r2, r3, st + OF_BL + bOff[bi] + ko);
                bl[bi*2+0][0] = r0; bl[bi*2+0][1] = r2;
                bl[bi*2+1][0] = r1; bl[bi*2+1][1] = r3;
            }
            #pragma unroll
            for (int mi = 0; mi < MF; mi++) {
                uint32_t ah[4], al[4];
                ldsm_x4(ah[0], ah[1], ah[2], ah[3], st + aOff[mi] + ko);
                ldsm_x4(al[0], al[1], al[2], al[3], st + OF_AL + aOff[mi] + ko);
                #pragma unroll
                for (int ni = 0; ni < NF; ni++) {
                    mma16816(acc[mi][ni], ah, bh[ni]);
                    mma16816(acc[mi][ni], al, bh[ni]);
                    mma16816(acc[mi][ni], ah, bl[ni]);
                }
            }
        }
    }

    // ---- epilogue ----
    if constexpr (MODE == 4) {
        // fused LSTM: thread owns all 4 gates of its units in registers
        const int q = lane & 3;
        const int wtile = (bn + n_base) >> 6;
        #pragma unroll
        for (int mi = 0; mi < MF; mi++) {
            #pragma unroll
            for (int v = 0; v < 2; v++) {
                const int row = bm + m_base + mi * 16 + (lane >> 2) + v * 8;
                const int ch = text[row * SS + s];
                const float* ep = g_ep + (size_t)ch * GG;
                #pragma unroll
                for (int r = 0; r < 2; r++) {
                    #pragma unroll
                    for (int e = 0; e < 2; e++) {
                        const int pb = bn + n_base + r * 32 + q * 2 + e;
                        const int u  = wtile * 16 + r * 8 + q * 2 + e;
                        float gi = acc[mi][4*r+0][v*2+e] + ep[pb];
                        float gf = acc[mi][4*r+1][v*2+e] + ep[pb + 8];
                        float gg = acc[mi][4*r+2][v*2+e] + ep[pb + 16];
                        float go = acc[mi][4*r+3][v*2+e] + ep[pb + 24];
                        float si = 1.f / (1.f + __expf(-gi));
                        float sf = 1.f / (1.f + __expf(-gf));
                        float so = 1.f / (1.f + __expf(-go));
                        size_t cix = (size_t)row * HH + u;
                        float cn = sf * g_c[cix] + si * tanhf(gg);
                        float hn = so * tanhf(cn);
                        g_c[cix] = cn;
                        __nv_bfloat16 hb, lb;
                        split2(hn, hb, lb);
                        g_xh_h[(size_t)row * KC + 512 + u] = hb;
                        g_xh_l[(size_t)row * KC + 512 + u] = lb;
                        g_h_h[cix] = hb;
                        g_h_l[cix] = lb;
                        size_t hsix = ((size_t)row * SS + s) * HH + u;
                        g_hs_h[hsix] = hb;
                        g_hs_l[hsix] = lb;
                    }
                }
            }
        }
    } else {
        #pragma unroll
        for (int mi = 0; mi < MF; mi++) {
            const int row0 = bm + m_base + mi * 16 + (lane >> 2);
            #pragma unroll
            for (int ni = 0; ni < NF; ni++) {
                const int col = bn + n_base + ni * 8 + (lane & 3) * 2;
                if constexpr (MODE == 1) {
                    float b0 = bias[col], b1 = bias[col + 1];
                    *(float2*)(C + (size_t)row0 * LDC + col) =
                        make_float2(acc[mi][ni][0] + b0, acc[mi][ni][1] + b1);
                    *(float2*)(C + (size_t)(row0 + 8) * LDC + col) =
                        make_float2(acc[mi][ni][2] + b0, acc[mi][ni][3] + b1);
                } else if constexpr (MODE == 3) {
                    *(__half2*)(C16 + (size_t)row0 * LDC + col) =
                        __floats2half2_rn(acc[mi][ni][0], acc[mi][ni][1]);
                    *(__half2*)(C16 + (size_t)(row0 + 8) * LDC + col) =
                        __floats2half2_rn(acc[mi][ni][2], acc[mi][ni][3]);
                } else { // MODE 2: N=97 tail
                    #pragma unroll
                    for (int h = 0; h < 2; h++) {
                        int cc = col + h;
                        if (cc < NC) {
                            float bb = bias[cc];
                            C[(size_t)row0 * LDC + cc]       = acc[mi][ni][0 + h] + bb;
                            C[(size_t)(row0 + 8) * LDC + cc] = acc[mi][ni][2 + h] + bb;
                        }
                    }
                }
            }
        }
    }
}

// ---------------- attention: scores + softmax + context (fp16 inputs) ------------
__global__ __launch_bounds__(256) void attn_step(const __half* __restrict__ Hp16,
                                                 const __half* __restrict__ bH16,
                                                 const float* __restrict__ wscore)
{
    const int b = blockIdx.x;
    const int tid = threadIdx.x;
    const int warp = tid >> 5, lane = tid & 31;
    __shared__ float sph[HH];
    __shared__ float sw[HH];
    __shared__ float se[32];

    const float* ph = g_ph + (size_t)b * HH;
    for (int i = tid; i < HH; i += 256) { sph[i] = ph[i]; sw[i] = wscore[i]; }
    __syncthreads();

    const __half2* Hpb = (const __half2*)(Hp16 + (size_t)b * TT * HH);
    for (int t = warp; t < TT; t += 8) {
        const __half2* hp = Hpb + t * (HH / 2);
        float s = 0.f;
        #pragma unroll
        for (int k2 = lane, it = 0; it < HH / 64; k2 += 32, it++) {
            float2 f = __half22float2(hp[k2]);
            s += sw[2*k2]   * tanh_fast(f.x + sph[2*k2]);
            s += sw[2*k2+1] * tanh_fast(f.y + sph[2*k2+1]);
        }
        #pragma unroll
        for (int o = 16; o > 0; o >>= 1) s += __shfl_down_sync(0xffffffffu, s, o);
        if (lane == 0) se[t] = s;
    }
    __syncthreads();

    if (tid < 32) {
        float v = (tid < TT) ? se[tid] : -1e30f;
        float m = v;
        #pragma unroll
        for (int o = 16; o > 0; o >>= 1) m = fmaxf(m, __shfl_xor_sync(0xffffffffu, m, o));
        float ex = (tid < TT) ? __expf(v - m) : 0.f;
        float sum = ex;
        #pragma unroll
        for (int o = 16; o > 0; o >>= 1) sum += __shfl_xor_sync(0xffffffffu, sum, o);
        if (tid < TT) se[tid] = ex / sum;
    }
    __syncthreads();

    const __half2* bH = (const __half2*)(bH16 + (size_t)b * TT * DD);
    {
        const int d2 = tid;               // 256 threads x half2 = 512 cols
        float ax = 0.f, ay = 0.f;
        #pragma unroll
        for (int t = 0; t < TT; t++) {
            float2 f = __half22float2(bH[t * (DD / 2) + d2]);
            float a = se[t];
            ax += a * f.x; ay += a * f.y;
        }
        __nv_bfloat16 h0, l0, h1, l1;
        split2(ax, h0, l0); split2(ay, h1, l1);
        size_t base = (size_t)b * KC + d2 * 2;
        g_xh_h[base] = h0;     g_xh_l[base] = l0;
        g_xh_h[base + 1] = h1; g_xh_l[base + 1] = l1;
    }
}

// ---------------- prep kernels -------------------------------------------------------
__global__ void prep_wcat_perm(const float* __restrict__ W_ih, const float* __restrict__ W_hh)
{
    int idx = blockIdx.x * blockDim.x + threadIdx.x;
    if (idx >= GG * KC) return;
    int p = idx >> 10, k = idx & 1023;
    int orow = perm_orig_row(p);
    float w = (k < 512) ? W_ih[orow * 768 + k] : W_hh[orow * 512 + k - 512];
    __nv_bfloat16 h, l; split2(w, h, l);
    g_Wcat_h[idx] = h; g_Wcat_l[idx] = l;
}

// permuted embproj with bias folded in: ep[c][p] = emb[c]·W_ih[orow,512:768] + b_ih[orow] + b_hh[orow]
__global__ __launch_bounds__(256) void prep_ep(const float* __restrict__ emb,
                                               const float* __restrict__ W_ih,
                                               const float* __restrict__ b_ih,
                                               const float* __restrict__ b_hh)
{
    int c = blockIdx.x;
    __shared__ float s_e[EE];
    for (int i = threadIdx.x; i < EE; i += 256) s_e[i] = emb[c * EE + i];
    __syncthreads();
    for (int p = threadIdx.x; p < GG; p += 256) {
        int orow = perm_orig_row(p);
        const float* w = W_ih + (size_t)orow * 768 + 512;
        float acc = b_ih[orow] + b_hh[orow];
        #pragma unroll 8
        for (int e = 0; e < EE; e++) acc += s_e[e] * w[e];
        g_ep[(size_t)c * GG + p] = acc;
    }
}

template<int W>
__global__ void prep_w512(const float* __restrict__ src)
{
    int idx = blockIdx.x * blockDim.x + threadIdx.x;
    if (idx >= HH * DD) return;
    float v = src[idx];
    __nv_bfloat16 h, l; split2(v, h, l);
    if (W == 0) { g_Wi2h_h[idx] = h; g_Wi2h_l[idx] = l; }
    else        { g_Wh2h_h[idx] = h; g_Wh2h_l[idx] = l; }
}

__global__ void prep_wgen(const float* __restrict__ W_gen)
{
    int idx = blockIdx.x * blockDim.x + threadIdx.x;
    if (idx >= 128 * DD) return;
    int n = idx >> 9;
    float v = (n < NC) ? W_gen[(size_t)n * DD + (idx & 511)] : 0.f;
    __nv_bfloat16 h, l; split2(v, h, l);
    g_Wgen_h[idx] = h; g_Wgen_l[idx] = l;
}

__global__ void prep_bh(const float* __restrict__ batch_H)
{
    int idx = blockIdx.x * blockDim.x + threadIdx.x;
    if (idx >= BB * TT * DD) return;
    float v = batch_H[idx];
    __nv_bfloat16 h, l; split2(v, h, l);
    g_bH_h[idx] = h; g_bH_l[idx] = l;
    g_bH16[idx] = __float2half_rn(v);
}

__global__ void prep_state()
{
    int idx = blockIdx.x * blockDim.x + threadIdx.x;
    if (idx >= BB * HH) return;
    g_c[idx] = 0.f;
    int b = idx >> 9, j = idx & 511;
    __nv_bfloat16 z = __float2bfloat16_rn(0.f);
    g_xh_h[(size_t)b * KC + 512 + j] = z;
    g_xh_l[(size_t)b * KC + 512 + j] = z;
    g_h_h[idx] = z; g_h_l[idx] = z;
}

// ---------------- launch --------------------------------------------------------------
extern "C" void kernel_launch(void* const* d_in, const int* in_sizes, int n_in,
                              void* d_out, int out_size)
{
    const float* batch_H  = (const float*)d_in[0];
    const int*   text     = (const int*)  d_in[1];
    const float* W_i2h    = (const float*)d_in[2];
    const float* W_h2h    = (const float*)d_in[3];
    const float* b_h2h    = (const float*)d_in[4];
    const float* w_score  = (const float*)d_in[5];
    const float* W_ih     = (const float*)d_in[6];
    const float* W_hh     = (const float*)d_in[7];
    const float* b_ih     = (const float*)d_in[8];
    const float* b_hh     = (const float*)d_in[9];
    const float* W_gen    = (const float*)d_in[10];
    const float* b_gen    = (const float*)d_in[11];
    const float* emb      = (const float*)d_in[12];
    float* out = (float*)d_out;

    static __nv_bfloat16 *p_xh_h, *p_xh_l, *p_h_h, *p_h_l, *p_hs_h, *p_hs_l,
                         *p_bH_h, *p_bH_l, *p_Wc_h, *p_Wc_l, *p_Wi_h, *p_Wi_l,
                         *p_Wh_h, *p_Wh_l, *p_Wg_h, *p_Wg_l;
    static float *p_ph;
    static __half *p_Hp16, *p_bH16;
    static bool init = false;
    if (!init) {
        cudaGetSymbolAddress((void**)&p_xh_h, g_xh_h);
        cudaGetSymbolAddress((void**)&p_xh_l, g_xh_l);
        cudaGetSymbolAddress((void**)&p_h_h,  g_h_h);
        cudaGetSymbolAddress((void**)&p_h_l,  g_h_l);
        cudaGetSymbolAddress((void**)&p_hs_h, g_hs_h);
        cudaGetSymbolAddress((void**)&p_hs_l, g_hs_l);
        cudaGetSymbolAddress((void**)&p_bH_h, g_bH_h);
        cudaGetSymbolAddress((void**)&p_bH_l, g_bH_l);
        cudaGetSymbolAddress((void**)&p_Wc_h, g_Wcat_h);
        cudaGetSymbolAddress((void**)&p_Wc_l, g_Wcat_l);
        cudaGetSymbolAddress((void**)&p_Wi_h, g_Wi2h_h);
        cudaGetSymbolAddress((void**)&p_Wi_l, g_Wi2h_l);
        cudaGetSymbolAddress((void**)&p_Wh_h, g_Wh2h_h);
        cudaGetSymbolAddress((void**)&p_Wh_l, g_Wh2h_l);
        cudaGetSymbolAddress((void**)&p_Wg_h, g_Wgen_h);
        cudaGetSymbolAddress((void**)&p_Wg_l, g_Wgen_l);
        cudaGetSymbolAddress((void**)&p_ph,   g_ph);
        cudaGetSymbolAddress((void**)&p_Hp16, g_Hp16);
        cudaGetSymbolAddress((void**)&p_bH16, g_bH16);
        init = true;
    }

    auto kHp    = hgemm<128,256,64,64,256, DD, HH, 3>;
    auto kPh    = hgemm< 64,128,32,64,128, DD, HH, 1>;
    auto kGates = hgemm<128,256,64,64,256, KC, GG, 4>;
    auto kGen   = hgemm<128,128,64,32,256, DD, NC, 2>;

    const int smHp    = 3 * 2 * (128 + 256) * 80;   // 184320
    const int smPh    = 3 * 2 * ( 64 + 128) * 80;   // 92160
    const int smGates = smHp;
    const int smGen   = 3 * 2 * (128 + 128) * 80;   // 122880
    cudaFuncSetAttribute(kHp,    cudaFuncAttributeMaxDynamicSharedMemorySize, smHp);
    cudaFuncSetAttribute(kPh,    cudaFuncAttributeMaxDynamicSharedMemorySize, smPh);
    cudaFuncSetAttribute(kGates, cudaFuncAttributeMaxDynamicSharedMemorySize, smGates);
    cudaFuncSetAttribute(kGen,   cudaFuncAttributeMaxDynamicSharedMemorySize, smGen);

    // prologue
    prep_wcat_perm<<<(GG * KC + 255) / 256, 256>>>(W_ih, W_hh);
    prep_ep<<<NC, 256>>>(emb, W_ih, b_ih, b_hh);
    prep_w512<0><<<(HH * DD + 255) / 256, 256>>>(W_i2h);
    prep_w512<1><<<(HH * DD + 255) / 256, 256>>>(W_h2h);
    prep_wgen<<<(128 * DD + 255) / 256, 256>>>(W_gen);
    prep_bh<<<(BB * TT * DD + 255) / 256, 256>>>(batch_H);
    prep_state<<<(BB * HH + 255) / 256, 256>>>();

    // Hp (fp16 out)
    kHp<<<dim3(HH/256, (BB*TT)/128), 256, smHp>>>(p_bH_h, p_bH_l, p_Wi_h, p_Wi_l,
                                                  nullptr, nullptr, p_Hp16, nullptr, 0);

    // 32 decode steps
    for (int s = 0; s < SS; s++) {
        kPh<<<dim3(HH/128, BB/64), 128, smPh>>>(p_h_h, p_h_l, p_Wh_h, p_Wh_l,
                                                b_h2h, p_ph, nullptr, nullptr, 0);
        attn_step<<<BB, 256>>>(p_Hp16, p_bH16, w_score);
        kGates<<<dim3(GG/256, BB/128), 256, smGates>>>(p_xh_h, p_xh_l, p_Wc_h, p_Wc_l,
                                                       nullptr, nullptr, nullptr, text, s);
    }

    // probs = hs @ W_gen^T + b_gen
    kGen<<<dim3(1, (BB*SS)/128), 256, smGen>>>(p_hs_h, p_hs_l, p_Wg_h, p_Wg_l,
                                               b_gen, out, nullptr, nullptr, 0);
}

// round 8
// speedup vs baseline: 1.2537x; 1.0256x over previous
#include <cuda_runtime.h>
#include <cuda_bf16.h>
#include <cuda_fp16.h>
#include <cstdint>

#define BB 2048
#define TT 26
#define DD 512
#define HH 512
#define EE 256
#define NC 97
#define SS 32
#define GG 2048   // 4*H
#define KC 1024   // concat K = D + H

// ---------------- scratch (static device memory; no allocations) ----------------
__device__ alignas(256) float g_c[(size_t)BB*HH];
__device__ alignas(256) float g_ph[(size_t)BB*HH];
__device__ alignas(256) float g_ep[(size_t)NC*GG];            // permuted embproj + bias
__device__ alignas(256) __half g_Hp16[(size_t)BB*TT*HH];
__device__ alignas(256) __half g_bH16[(size_t)BB*TT*DD];
// pre-split bf16 hi/lo planes (x = hi + lo)
__device__ alignas(256) __nv_bfloat16 g_xh_h[(size_t)BB*KC], g_xh_l[(size_t)BB*KC];
__device__ alignas(256) __nv_bfloat16 g_hs_h[(size_t)BB*SS*DD], g_hs_l[(size_t)BB*SS*DD];
__device__ alignas(256) __nv_bfloat16 g_bH_h[(size_t)BB*TT*DD], g_bH_l[(size_t)BB*TT*DD];
__device__ alignas(256) __nv_bfloat16 g_Wcat_h[(size_t)GG*KC], g_Wcat_l[(size_t)GG*KC]; // PERMUTED
__device__ alignas(256) __nv_bfloat16 g_Wi2h_h[(size_t)HH*DD], g_Wi2h_l[(size_t)HH*DD];
__device__ alignas(256) __nv_bfloat16 g_Wh2h_h[(size_t)HH*DD], g_Wh2h_l[(size_t)HH*DD];
__device__ alignas(256) __nv_bfloat16 g_Wgen_h[(size_t)128*DD], g_Wgen_l[(size_t)128*DD];

// gate-interleave permutation: physical col p <-> (gate g, unit u)
__device__ __host__ __forceinline__ int perm_orig_row(int p) {
    int w = p >> 6, m = p & 63;
    int ni = m >> 3, r = ni >> 2, g = ni & 3;
    int q = (m >> 1) & 3, e = m & 1;
    int u = w * 16 + r * 8 + q * 2 + e;
    return g * 512 + u;
}

// ================= helpers =================
__device__ __forceinline__ uint32_t smem_u32(const void* p) {
    uint32_t a;
    asm("{ .reg .u64 t; cvta.to.shared.u64 t, %1; cvt.u32.u64 %0, t; }" : "=r"(a) : "l"(p));
    return a;
}
__device__ __forceinline__ void ldsm_x4(uint32_t& r0, uint32_t& r1, uint32_t& r2, uint32_t& r3,
                                        uint32_t addr) {
    asm volatile("ldmatrix.sync.aligned.m8n8.x4.shared.b16 {%0,%1,%2,%3}, [%4];"
                 : "=r"(r0), "=r"(r1), "=r"(r2), "=r"(r3) : "r"(addr));
}
__device__ __forceinline__ void mma16816(float* d, const uint32_t* a, const uint32_t* b) {
    asm volatile(
        "mma.sync.aligned.m16n8k16.row.col.f32.bf16.bf16.f32 "
        "{%0,%1,%2,%3}, {%4,%5,%6,%7}, {%8,%9}, {%0,%1,%2,%3};"
        : "+f"(d[0]), "+f"(d[1]), "+f"(d[2]), "+f"(d[3])
        : "r"(a[0]), "r"(a[1]), "r"(a[2]), "r"(a[3]), "r"(b[0]), "r"(b[1]));
}
__device__ __forceinline__ void cp16(uint32_t dst, const void* src) {
    asm volatile("cp.async.cg.shared.global [%0], [%1], 16;" :: "r"(dst), "l"(src));
}
#define CP_COMMIT asm volatile("cp.async.commit_group;")
#define CP_WAIT1  asm volatile("cp.async.wait_group 1;")
__device__ __forceinline__ float tanh_fast(float x) {
    float r;
    asm("tanh.approx.f32 %0, %1;" : "=f"(r) : "f"(x));
    return r;
}
__device__ __forceinline__ void split2(float x, __nv_bfloat16& h, __nv_bfloat16& l) {
    h = __float2bfloat16_rn(x);
    l = __float2bfloat16_rn(x - __bfloat162float(h));
}

// ================= hi/lo-plane bf16 HMMA GEMM, 3-term split ======================
// MODE 1: fp32 out + bias (ph)   MODE 2: fp32 out + bias, N=97 tail (generator)
// MODE 3: fp16 out, no bias (Hp) MODE 4: fused LSTM epilogue (gates)
template<int BM, int BN, int WM, int WN, int TH, int K, int LDA, int LDC, int MODE>
__global__ __launch_bounds__(TH, 1)
void hgemm(const __nv_bfloat16* __restrict__ Ah, const __nv_bfloat16* __restrict__ Al,
           const __nv_bfloat16* __restrict__ Bh, const __nv_bfloat16* __restrict__ Bl,
           const float* __restrict__ bias, float* __restrict__ C,
           __half* __restrict__ C16, const int* __restrict__ text, int s)
{
    constexpr int NCH = K / 32;
    constexpr int MF = WM / 16;
    constexpr int NF = WN / 8;
    constexpr int NFB = WN / 16;
    constexpr int NWN = BN / WN;
    constexpr int OF_AL = BM * 80;
    constexpr int OF_BH = 2 * BM * 80;
    constexpr int OF_BL = 2 * BM * 80 + BN * 80;
    constexpr int STAGEB = 2 * (BM + BN) * 80;

    extern __shared__ char smc[];
    const int tid = threadIdx.x, wid = tid >> 5, lane = tid & 31;
    const int bm = blockIdx.y * BM, bn = blockIdx.x * BN;
    const uint32_t sb = smem_u32(smc);

    const __nv_bfloat16* Ahg = Ah + (size_t)bm * LDA;
    const __nv_bfloat16* Alg = Al + (size_t)bm * LDA;
    const __nv_bfloat16* Bhg = Bh + (size_t)bn * K;
    const __nv_bfloat16* Blg = Bl + (size_t)bn * K;

    auto issue = [&](int ch, int slot) {
        const uint32_t st = sb + (uint32_t)(slot * STAGEB);
        const int kof = ch * 32;
        #pragma unroll
        for (int i = 0; i < (BM * 4) / TH; i++) {
            int idx = tid + i * TH, row = idx >> 2, q = idx & 3;
            cp16(st + row * 80 + q * 16, Ahg + (size_t)row * LDA + kof + q * 8);
        }
        #pragma unroll
        for (int i = 0; i < (BM * 4) / TH; i++) {
            int idx = tid + i * TH, row = idx >> 2, q = idx & 3;
            cp16(st + OF_AL + row * 80 + q * 16, Alg + (size_t)row * LDA + kof + q * 8);
        }
        #pragma unroll
        for (int i = 0; i < (BN * 4) / TH; i++) {
            int idx = tid + i * TH, row = idx >> 2, q = idx & 3;
            cp16(st + OF_BH + row * 80 + q * 16, Bhg + (size_t)row * K + kof + q * 8);
        }
        #pragma unroll
        for (int i = 0; i < (BN * 4) / TH; i++) {
            int idx = tid + i * TH, row = idx >> 2, q = idx & 3;
            cp16(st + OF_BL + row * 80 + q * 16, Blg + (size_t)row * K + kof + q * 8);
        }
        CP_COMMIT;
    };

    const int m_base = (wid / NWN) * WM;
    const int n_base = (wid % NWN) * WN;

    uint32_t aOff[MF], bOff[NFB];
    #pragma unroll
    for (int mi = 0; mi < MF; mi++)
        aOff[mi] = (uint32_t)((m_base + mi * 16 + (lane & 15)) * 80 + (lane >> 4) * 16);
    #pragma unroll
    for (int bi = 0; bi < NFB; bi++)
        bOff[bi] = (uint32_t)((n_base + bi * 16 + (lane & 15)) * 80 + (lane >> 4) * 16);

    float acc[MF][NF][4];
    #pragma unroll
    for (int mi = 0; mi < MF; mi++)
        #pragma unroll
        for (int ni = 0; ni < NF; ni++)
            #pragma unroll
            for (int i = 0; i < 4; i++) acc[mi][ni][i] = 0.f;

    issue(0, 0);
    issue(1, 1);

    for (int c = 0; c < NCH; c++) {
        const int slot = c % 3;
        CP_WAIT1;
        __syncthreads();
        if (c + 2 < NCH) issue(c + 2, (c + 2) % 3);
        else CP_COMMIT;

        const uint32_t st = sb + (uint32_t)(slot * STAGEB);
        #pragma unroll
        for (int k16 = 0; k16 < 2; k16++) {
            const uint32_t ko = k16 * 32;
            uint32_t bh[NF][2], bl[NF][2];
            #pragma unroll
            for (int bi = 0; bi < NFB; bi++) {
                uint32_t r0, r1, r2, r3;
                ldsm_x4(r0, r1, r2, r3, st + OF_BH + bOff[bi] + ko);
                bh[bi*2+0][0] = r0; bh[bi*2+0][1] = r2;
                bh[bi*2+1][0] = r1; bh[bi*2+1][1] = r3;
                ldsm_x4(r0, r1, r2, r3, st + OF_BL + bOff[bi] + ko);
                bl[bi*2+0][0] = r0; bl[bi*2+0][1] = r2;
                bl[bi*2+1][0] = r1; bl[bi*2+1][1] = r3;
            }
            #pragma unroll
            for (int mi = 0; mi < MF; mi++) {
                uint32_t ah[4], al[4];
                ldsm_x4(ah[0], ah[1], ah[2], ah[3], st + aOff[mi] + ko);
                ldsm_x4(al[0], al[1], al[2], al[3], st + OF_AL + aOff[mi] + ko);
                #pragma unroll
                for (int ni = 0; ni < NF; ni++) {
                    mma16816(acc[mi][ni], ah, bh[ni]);
                    mma16816(acc[mi][ni], al, bh[ni]);
                    mma16816(acc[mi][ni], ah, bl[ni]);
                }
            }
        }
    }

    // ---- epilogue ----
    if constexpr (MODE == 4) {
        const int q = lane & 3;
        const int wtile = (bn + n_base) >> 6;
        #pragma unroll
        for (int mi = 0; mi < MF; mi++) {
            #pragma unroll
            for (int v = 0; v < 2; v++) {
                const int row = bm + m_base + mi * 16 + (lane >> 2) + v * 8;
                const int ch = text[row * SS + s];
                const float* ep = g_ep + (size_t)ch * GG;
                #pragma unroll
                for (int r = 0; r < 2; r++) {
                    #pragma unroll
                    for (int e = 0; e < 2; e++) {
                        const int pb = bn + n_base + r * 32 + q * 2 + e;
                        const int u  = wtile * 16 + r * 8 + q * 2 + e;
                        float gi = acc[mi][4*r+0][v*2+e] + ep[pb];
                        float gf = acc[mi][4*r+1][v*2+e] + ep[pb + 8];
                        float gg = acc[mi][4*r+2][v*2+e] + ep[pb + 16];
                        float go = acc[mi][4*r+3][v*2+e] + ep[pb + 24];
                        float si = 1.f / (1.f + __expf(-gi));
                        float sf = 1.f / (1.f + __expf(-gf));
                        float so = 1.f / (1.f + __expf(-go));
                        size_t cix = (size_t)row * HH + u;
                        float cn = sf * g_c[cix] + si * tanhf(gg);
                        float hn = so * tanhf(cn);
                        g_c[cix] = cn;
                        __nv_bfloat16 hb, lb;
                        split2(hn, hb, lb);
                        g_xh_h[(size_t)row * KC + 512 + u] = hb;
                        g_xh_l[(size_t)row * KC + 512 + u] = lb;
                        size_t hsix = ((size_t)row * SS + s) * HH + u;
                        g_hs_h[hsix] = hb;
                        g_hs_l[hsix] = lb;
                    }
                }
            }
        }
    } else {
        #pragma unroll
        for (int mi = 0; mi < MF; mi++) {
            const int row0 = bm + m_base + mi * 16 + (lane >> 2);
            #pragma unroll
            for (int ni = 0; ni < NF; ni++) {
                const int col = bn + n_base + ni * 8 + (lane & 3) * 2;
                if constexpr (MODE == 1) {
                    float b0 = bias[col], b1 = bias[col + 1];
                    *(float2*)(C + (size_t)row0 * LDC + col) =
                        make_float2(acc[mi][ni][0] + b0, acc[mi][ni][1] + b1);
                    *(float2*)(C + (size_t)(row0 + 8) * LDC + col) =
                        make_float2(acc[mi][ni][2] + b0, acc[mi][ni][3] + b1);
                } else if constexpr (MODE == 3) {
                    *(__half2*)(C16 + (size_t)row0 * LDC + col) =
                        __floats2half2_rn(acc[mi][ni][0], acc[mi][ni][1]);
                    *(__half2*)(C16 + (size_t)(row0 + 8) * LDC + col) =
                        __floats2half2_rn(acc[mi][ni][2], acc[mi][ni][3]);
                } else { // MODE 2
                    #pragma unroll
                    for (int h = 0; h < 2; h++) {
                        int cc = col + h;
                        if (cc < NC) {
                            float bb = bias[cc];
                            C[(size_t)row0 * LDC + cc]       = acc[mi][ni][0 + h] + bb;
                            C[(size_t)(row0 + 8) * LDC + cc] = acc[mi][ni][2 + h] + bb;
                        }
                    }
                }
            }
        }
    }
}

// ---------------- attention: scores + softmax + context (fp16 inputs) ------------
__global__ __launch_bounds__(256) void attn_step(const __half* __restrict__ Hp16,
                                                 const __half* __restrict__ bH16,
                                                 const float* __restrict__ wscore)
{
    const int b = blockIdx.x;
    const int tid = threadIdx.x;
    const int warp = tid >> 5, lane = tid & 31;
    __shared__ float sph[HH];
    __shared__ float sw[HH];
    __shared__ float se[32];

    const float* ph = g_ph + (size_t)b * HH;
    for (int i = tid; i < HH; i += 256) { sph[i] = ph[i]; sw[i] = wscore[i]; }
    __syncthreads();

    const __half2* Hpb = (const __half2*)(Hp16 + (size_t)b * TT * HH);
    for (int t = warp; t < TT; t += 8) {
        const __half2* hp = Hpb + t * (HH / 2);
        float s = 0.f;
        #pragma unroll
        for (int k2 = lane, it = 0; it < HH / 64; k2 += 32, it++) {
            float2 f = __half22float2(hp[k2]);
            s += sw[2*k2]   * tanh_fast(f.x + sph[2*k2]);
            s += sw[2*k2+1] * tanh_fast(f.y + sph[2*k2+1]);
        }
        #pragma unroll
        for (int o = 16; o > 0; o >>= 1) s += __shfl_down_sync(0xffffffffu, s, o);
        if (lane == 0) se[t] = s;
    }
    __syncthreads();

    if (tid < 32) {
        float v = (tid < TT) ? se[tid] : -1e30f;
        float m = v;
        #pragma unroll
        for (int o = 16; o > 0; o >>= 1) m = fmaxf(m, __shfl_xor_sync(0xffffffffu, m, o));
        float ex = (tid < TT) ? __expf(v - m) : 0.f;
        float sum = ex;
        #pragma unroll
        for (int o = 16; o > 0; o >>= 1) sum += __shfl_xor_sync(0xffffffffu, sum, o);
        if (tid < TT) se[tid] = ex / sum;
    }
    __syncthreads();

    const __half2* bH = (const __half2*)(bH16 + (size_t)b * TT * DD);
    {
        const int d2 = tid;
        float ax = 0.f, ay = 0.f;
        #pragma unroll
        for (int t = 0; t < TT; t++) {
            float2 f = __half22float2(bH[t * (DD / 2) + d2]);
            float a = se[t];
            ax += a * f.x; ay += a * f.y;
        }
        __nv_bfloat16 h0, l0, h1, l1;
        split2(ax, h0, l0); split2(ay, h1, l1);
        size_t base = (size_t)b * KC + d2 * 2;
        g_xh_h[base] = h0;     g_xh_l[base] = l0;
        g_xh_h[base + 1] = h1; g_xh_l[base + 1] = l1;
    }
}

// ---------------- merged prep kernel (grid-stride over largest range) --------------
__global__ void prep_all(const float* __restrict__ W_ih, const float* __restrict__ W_hh,
                         const float* __restrict__ W_i2h, const float* __restrict__ W_h2h,
                         const float* __restrict__ W_gen, const float* __restrict__ batch_H)
{
    int idx = blockIdx.x * blockDim.x + threadIdx.x;

    if (idx < BB * TT * DD) {                        // batch_H splits + fp16 copy
        float v = batch_H[idx];
        __nv_bfloat16 h, l; split2(v, h, l);
        g_bH_h[idx] = h; g_bH_l[idx] = l;
        g_bH16[idx] = __float2half_rn(v);
    }
    if (idx < GG * KC) {                             // Wcat permuted split
        int p = idx >> 10, k = idx & 1023;
        int orow = perm_orig_row(p);
        float w = (k < 512) ? W_ih[orow * 768 + k] : W_hh[orow * 512 + k - 512];
        __nv_bfloat16 h, l; split2(w, h, l);
        g_Wcat_h[idx] = h; g_Wcat_l[idx] = l;
    }
    if (idx < HH * DD) {                             // W_i2h / W_h2h splits
        float v = W_i2h[idx];
        __nv_bfloat16 h, l; split2(v, h, l);
        g_Wi2h_h[idx] = h; g_Wi2h_l[idx] = l;
        v = W_h2h[idx];
        split2(v, h, l);
        g_Wh2h_h[idx] = h; g_Wh2h_l[idx] = l;
    }
    if (idx < 128 * DD) {                            // W_gen padded split
        int n = idx >> 9;
        float v = (n < NC) ? W_gen[(size_t)n * DD + (idx & 511)] : 0.f;
        __nv_bfloat16 h, l; split2(v, h, l);
        g_Wgen_h[idx] = h; g_Wgen_l[idx] = l;
    }
    if (idx < BB * HH) {                             // state init
        g_c[idx] = 0.f;
        int b = idx >> 9, j = idx & 511;
        __nv_bfloat16 z = __float2bfloat16_rn(0.f);
        g_xh_h[(size_t)b * KC + 512 + j] = z;
        g_xh_l[(size_t)b * KC + 512 + j] = z;
    }
}

__global__ __launch_bounds__(256) void prep_ep(const float* __restrict__ emb,
                                               const float* __restrict__ W_ih,
                                               const float* __restrict__ b_ih,
                                               const float* __restrict__ b_hh)
{
    int c = blockIdx.x;
    __shared__ float s_e[EE];
    for (int i = threadIdx.x; i < EE; i += 256) s_e[i] = emb[c * EE + i];
    __syncthreads();
    for (int p = threadIdx.x; p < GG; p += 256) {
        int orow = perm_orig_row(p);
        const float* w = W_ih + (size_t)orow * 768 + 512;
        float acc = b_ih[orow] + b_hh[orow];
        #pragma unroll 8
        for (int e = 0; e < EE; e++) acc += s_e[e] * w[e];
        g_ep[(size_t)c * GG + p] = acc;
    }
}

// ---------------- launch --------------------------------------------------------------
extern "C" void kernel_launch(void* const* d_in, const int* in_sizes, int n_in,
                              void* d_out, int out_size)
{
    const float* batch_H  = (const float*)d_in[0];
    const int*   text     = (const int*)  d_in[1];
    const float* W_i2h    = (const float*)d_in[2];
    const float* W_h2h    = (const float*)d_in[3];
    const float* b_h2h    = (const float*)d_in[4];
    const float* w_score  = (const float*)d_in[5];
    const float* W_ih     = (const float*)d_in[6];
    const float* W_hh     = (const float*)d_in[7];
    const float* b_ih     = (const float*)d_in[8];
    const float* b_hh     = (const float*)d_in[9];
    const float* W_gen    = (const float*)d_in[10];
    const float* b_gen    = (const float*)d_in[11];
    const float* emb      = (const float*)d_in[12];
    float* out = (float*)d_out;

    static __nv_bfloat16 *p_xh_h, *p_xh_l, *p_hs_h, *p_hs_l,
                         *p_bH_h, *p_bH_l, *p_Wc_h, *p_Wc_l, *p_Wi_h, *p_Wi_l,
                         *p_Wh_h, *p_Wh_l, *p_Wg_h, *p_Wg_l;
    static float *p_ph;
    static __half *p_Hp16, *p_bH16;
    static bool init = false;
    if (!init) {
        cudaGetSymbolAddress((void**)&p_xh_h, g_xh_h);
        cudaGetSymbolAddress((void**)&p_xh_l, g_xh_l);
        cudaGetSymbolAddress((void**)&p_hs_h, g_hs_h);
        cudaGetSymbolAddress((void**)&p_hs_l, g_hs_l);
        cudaGetSymbolAddress((void**)&p_bH_h, g_bH_h);
        cudaGetSymbolAddress((void**)&p_bH_l, g_bH_l);
        cudaGetSymbolAddress((void**)&p_Wc_h, g_Wcat_h);
        cudaGetSymbolAddress((void**)&p_Wc_l, g_Wcat_l);
        cudaGetSymbolAddress((void**)&p_Wi_h, g_Wi2h_h);
        cudaGetSymbolAddress((void**)&p_Wi_l, g_Wi2h_l);
        cudaGetSymbolAddress((void**)&p_Wh_h, g_Wh2h_h);
        cudaGetSymbolAddress((void**)&p_Wh_l, g_Wh2h_l);
        cudaGetSymbolAddress((void**)&p_Wg_h, g_Wgen_h);
        cudaGetSymbolAddress((void**)&p_Wg_l, g_Wgen_l);
        cudaGetSymbolAddress((void**)&p_ph,   g_ph);
        cudaGetSymbolAddress((void**)&p_Hp16, g_Hp16);
        cudaGetSymbolAddress((void**)&p_bH16, g_bH16);
        init = true;
    }

    auto kHp    = hgemm<128,256,64,64,256, DD, DD, HH, 3>;
    auto kPh    = hgemm< 64,128,32,64,128, DD, KC, HH, 1>;   // A = xh planes + 512, LDA=KC
    auto kGates = hgemm<128,256,64,64,256, KC, KC, GG, 4>;
    auto kGen   = hgemm<128,128,64,32,256, DD, DD, NC, 2>;

    const int smHp    = 3 * 2 * (128 + 256) * 80;
    const int smPh    = 3 * 2 * ( 64 + 128) * 80;
    const int smGates = smHp;
    const int smGen   = 3 * 2 * (128 + 128) * 80;
    cudaFuncSetAttribute(kHp,    cudaFuncAttributeMaxDynamicSharedMemorySize, smHp);
    cudaFuncSetAttribute(kPh,    cudaFuncAttributeMaxDynamicSharedMemorySize, smPh);
    cudaFuncSetAttribute(kGates, cudaFuncAttributeMaxDynamicSharedMemorySize, smGates);
    cudaFuncSetAttribute(kGen,   cudaFuncAttributeMaxDynamicSharedMemorySize, smGen);

    // prologue (2 launches so that launch #6 == kGates for ncu -s 5 -c 1)
    prep_all<<<(BB * TT * DD + 255) / 256, 256>>>(W_ih, W_hh, W_i2h, W_h2h, W_gen, batch_H);
    prep_ep<<<NC, 256>>>(emb, W_ih, b_ih, b_hh);

    // Hp (fp16 out)
    kHp<<<dim3(HH/256, (BB*TT)/128), 256, smHp>>>(p_bH_h, p_bH_l, p_Wi_h, p_Wi_l,
                                                  nullptr, nullptr, p_Hp16, nullptr, 0);

    // 32 decode steps
    for (int s = 0; s < SS; s++) {
        kPh<<<dim3(HH/128, BB/64), 128, smPh>>>(p_xh_h + 512, p_xh_l + 512, p_Wh_h, p_Wh_l,
                                                b_h2h, p_ph, nullptr, nullptr, 0);
        attn_step<<<BB, 256>>>(p_Hp16, p_bH16, w_score);
        kGates<<<dim3(GG/256, BB/128), 256, smGates>>>(p_xh_h, p_xh_l, p_Wc_h, p_Wc_l,
                                                       nullptr, nullptr, nullptr, text, s);
    }

    // probs = hs @ W_gen^T + b_gen
    kGen<<<dim3(1, (BB*SS)/128), 256, smGen>>>(p_hs_h, p_hs_l, p_Wg_h, p_Wg_l,
                                               b_gen, out, nullptr, nullptr, 0);
}